// round 11
// baseline (speedup 1.0000x reference)
#include <cuda_runtime.h>
#include <cstdint>

// out[c, i, j, k, l] = tb[c,0,i] * tb[c,1,j] * tb[c,2,k] * tb[c,3,l]
// tb = tensor + bias, shapes (C=2048, 4, 16). Output (C, 16,16,16,16) fp32.
//
// Pure store-bandwidth kernel: 512 MB out, ~1 MB in.
// R11: same work schedule as R7 (one 16KB i-slice per CTA, 26.9 waves,
// 96%-full tail) but with 512-thread CTAs -> grid halves to 16384.
// Each thread computes and stores exactly ONE float8 (st.global.v8).
// Motivation: wall-minus-ncu gap was 0.38us at 16384 CTAs (R6) vs
// ~2.1us at 32768 CTAs (R7/R9/R10) -> dispatch-count cost; this keeps
// R7's in-kernel schedule with R6's dispatch count.

static constexpr int LDIM = 16;
static constexpr int NFAC = 4;
static constexpr int THREADS = 512;

__device__ __forceinline__ void stg_v8(float* p,
                                       float a, float b, float c, float d,
                                       float e, float f, float g, float h)
{
    asm volatile(
        "st.global.v8.b32 [%0], {%1, %2, %3, %4, %5, %6, %7, %8};"
        :: "l"(p),
           "r"(__float_as_uint(a)), "r"(__float_as_uint(b)),
           "r"(__float_as_uint(c)), "r"(__float_as_uint(d)),
           "r"(__float_as_uint(e)), "r"(__float_as_uint(f)),
           "r"(__float_as_uint(g)), "r"(__float_as_uint(h))
        : "memory");
}

__global__ __launch_bounds__(THREADS, 4)
void tpe_kernel(const float* __restrict__ tensor,
                const float* __restrict__ bias,
                float* __restrict__ out)
{
    __shared__ float s[NFAC * LDIM];

    const int b = blockIdx.x;
    const int c = b >> 4;          // channel
    const int i = b & 15;          // i slice: this CTA writes out[c, i, :, :, :]
    const int t = threadIdx.x;

    if (t < NFAC * LDIM) {
        const int g = c * (NFAC * LDIM) + t;
        s[t] = tensor[g] + bias[g];
    }
    __syncthreads();

    // Thread t owns float8 index r = t within the i-slice (4096 floats):
    // element e = 8t: l-half lh = t & 1, k = (t>>1) & 15, j = (t>>5) & 15.
    const int lh = t & 1;
    const int k  = (t >> 1) & 15;
    const int j  = (t >> 5) & 15;

    const float a = s[i] * s[2 * LDIM + k] * s[LDIM + j];
    const float* v3 = s + 3 * LDIM + lh * 8;

    float* ob = out + (size_t)c * 65536 + (size_t)i * 4096 + (size_t)t * 8;

    stg_v8(ob,
           a * v3[0], a * v3[1], a * v3[2], a * v3[3],
           a * v3[4], a * v3[5], a * v3[6], a * v3[7]);
}

extern "C" void kernel_launch(void* const* d_in, const int* in_sizes, int n_in,
                              void* d_out, int out_size)
{
    const float* tensor = (const float*)d_in[0];
    const float* bias   = (const float*)d_in[1];
    float* out          = (float*)d_out;

    const int C = in_sizes[0] / (NFAC * LDIM);   // 2048

    tpe_kernel<<<C * 16, THREADS>>>(tensor, bias, out);
}

// round 12
// speedup vs baseline: 1.3150x; 1.3150x over previous
#include <cuda_runtime.h>
#include <cstdint>

// out[c, i, j, k, l] = tb[c,0,i] * tb[c,1,j] * tb[c,2,k] * tb[c,3,l]
// tb = tensor + bias, shapes (C=2048, 4, 16). Output (C, 16,16,16,16) fp32.
//
// Pure store-bandwidth kernel: 512 MB out, ~1 MB in.
// R12 = R6's schedule (16384 CTAs, 32KB per CTA, lowest measured
// dispatch overhead) with 512-thread blocks: each CTA covers TWO
// i-slices; each thread computes and stores two independent float8s
// (st.global.v8). 16 warps/CTA, 4 CTAs/SM = 64 warps resident.
// R11's failure mode (1 store/thread -> prologue-dominated CTAs,
// DRAM 62%) is fixed by the 2-slice coverage.

static constexpr int LDIM = 16;
static constexpr int NFAC = 4;
static constexpr int THREADS = 512;

__device__ __forceinline__ void stg_v8(float* p,
                                       float a, float b, float c, float d,
                                       float e, float f, float g, float h)
{
    asm volatile(
        "st.global.v8.b32 [%0], {%1, %2, %3, %4, %5, %6, %7, %8};"
        :: "l"(p),
           "r"(__float_as_uint(a)), "r"(__float_as_uint(b)),
           "r"(__float_as_uint(c)), "r"(__float_as_uint(d)),
           "r"(__float_as_uint(e)), "r"(__float_as_uint(f)),
           "r"(__float_as_uint(g)), "r"(__float_as_uint(h))
        : "memory");
}

__global__ __launch_bounds__(THREADS, 4)
void tpe_kernel(const float* __restrict__ tensor,
                const float* __restrict__ bias,
                float* __restrict__ out)
{
    __shared__ float s[NFAC * LDIM];

    const int b  = blockIdx.x;
    const int c  = b >> 3;         // channel
    const int ih = b & 7;          // i-pair: slices i0 = 2*ih, i0+1
    const int t  = threadIdx.x;

    if (t < NFAC * LDIM) {
        const int g = c * (NFAC * LDIM) + t;
        s[t] = tensor[g] + bias[g];
    }
    __syncthreads();

    // Within one i-slice (4096 floats), float8 index r in [0,512):
    //   lh = r & 1, k = (r>>1) & 15, j = (r>>5) & 15.
    // Thread t handles r = t in slice i0 and r = t in slice i0+1.
    const int lh = t & 1;
    const int k  = (t >> 1) & 15;
    const int j  = (t >> 5) & 15;

    const float pkj = s[2 * LDIM + k] * s[LDIM + j];
    const int   i0  = ih << 1;
    const float a0  = s[i0]     * pkj;
    const float a1  = s[i0 + 1] * pkj;

    const float* v3 = s + 3 * LDIM + lh * 8;
    float w0 = v3[0], w1 = v3[1], w2 = v3[2], w3 = v3[3];
    float w4 = v3[4], w5 = v3[5], w6 = v3[6], w7 = v3[7];

    float* ob = out + (size_t)c * 65536 + (size_t)i0 * 4096 + (size_t)t * 8;

    stg_v8(ob,
           a0 * w0, a0 * w1, a0 * w2, a0 * w3,
           a0 * w4, a0 * w5, a0 * w6, a0 * w7);
    stg_v8(ob + 4096,
           a1 * w0, a1 * w1, a1 * w2, a1 * w3,
           a1 * w4, a1 * w5, a1 * w6, a1 * w7);
}

extern "C" void kernel_launch(void* const* d_in, const int* in_sizes, int n_in,
                              void* d_out, int out_size)
{
    const float* tensor = (const float*)d_in[0];
    const float* bias   = (const float*)d_in[1];
    float* out          = (float*)d_out;

    const int C = in_sizes[0] / (NFAC * LDIM);   // 2048

    tpe_kernel<<<C * 8, THREADS>>>(tensor, bias, out);
}

// round 13
// speedup vs baseline: 1.3476x; 1.0248x over previous
#include <cuda_runtime.h>
#include <cstdint>

// out[c, i, j, k, l] = tb[c,0,i] * tb[c,1,j] * tb[c,2,k] * tb[c,3,l]
// tb = tensor + bias, shapes (C=2048, 4, 16). Output (C, 16,16,16,16) fp32.
//
// FINAL (= R7, session best: 75.84us wall, ncu 73.8us, DRAM 81.6%,
// 7.3 TB/s effective store rate = 91% of HBM3e spec).
//
// Pure store-bandwidth kernel: 512 MB out, ~1 MB in. Converged config:
//  - 32768 CTAs x 256 threads; each CTA writes one contiguous 16 KB
//    i-slice out[c, i, :, :, :]  (26.9-wave schedule, 96%-full tail wave
//    -> tail quantization eliminated; validated R4->R5->R6->R7).
//  - smem-staged inputs (64 floats, one barrier) — beats direct per-thread
//    LDG (R8) by keeping the L1/LSU input traffic off the store stream.
//  - 256-bit st.global.v8.b32 stores, 2 independent per thread, perfectly
//    coalesced 128B lines (beats STG.128, R4).
//  - plain STG egress: measured identical to 16KB and per-warp 1KB
//    cp.async.bulk (R9/R10) — LTS/DRAM path-independent; fewest moving parts.

static constexpr int LDIM = 16;
static constexpr int NFAC = 4;
static constexpr int THREADS = 256;

__device__ __forceinline__ void stg_v8(float* p,
                                       float a, float b, float c, float d,
                                       float e, float f, float g, float h)
{
    asm volatile(
        "st.global.v8.b32 [%0], {%1, %2, %3, %4, %5, %6, %7, %8};"
        :: "l"(p),
           "r"(__float_as_uint(a)), "r"(__float_as_uint(b)),
           "r"(__float_as_uint(c)), "r"(__float_as_uint(d)),
           "r"(__float_as_uint(e)), "r"(__float_as_uint(f)),
           "r"(__float_as_uint(g)), "r"(__float_as_uint(h))
        : "memory");
}

__global__ __launch_bounds__(THREADS, 8)
void tpe_kernel(const float* __restrict__ tensor,
                const float* __restrict__ bias,
                float* __restrict__ out)
{
    __shared__ float s[NFAC * LDIM];

    const int b = blockIdx.x;
    const int c = b >> 4;          // channel
    const int i = b & 15;          // i slice: this CTA writes out[c, i, :, :, :]
    const int t = threadIdx.x;

    if (t < NFAC * LDIM) {
        const int g = c * (NFAC * LDIM) + t;
        s[t] = tensor[g] + bias[g];
    }
    __syncthreads();

    const float* s0 = s;               // i
    const float* s1 = s + LDIM;        // j
    const float* s2 = s + 2 * LDIM;    // k
    const float* s3 = s + 3 * LDIM;    // l

    // float8 index within the i-slice: r = t + 256*jh, jh in {0,1}.
    //   l-half lh = r & 1, k = (r>>1) & 15, jlow = (r>>5) & 7 (from t);
    //   j = jlow | (jh<<3).
    const int lh   = t & 1;
    const int k    = (t >> 1) & 15;
    const int jlow = (t >> 5) & 7;

    const float p2 = s2[k];
    float v3[8];
    #pragma unroll
    for (int m = 0; m < 8; ++m) v3[m] = s3[lh * 8 + m];

    const float a0 = s0[i] * p2;

    float* ob = out + (size_t)c * 65536 + (size_t)i * 4096 + (size_t)t * 8;

    #pragma unroll
    for (int jh = 0; jh < 2; ++jh) {
        const float a = a0 * s1[jlow + (jh << 3)];
        stg_v8(ob + (size_t)jh * 2048,
               a * v3[0], a * v3[1], a * v3[2], a * v3[3],
               a * v3[4], a * v3[5], a * v3[6], a * v3[7]);
    }
}

extern "C" void kernel_launch(void* const* d_in, const int* in_sizes, int n_in,
                              void* d_out, int out_size)
{
    const float* tensor = (const float*)d_in[0];
    const float* bias   = (const float*)d_in[1];
    float* out          = (float*)d_out;

    const int C = in_sizes[0] / (NFAC * LDIM);   // 2048

    tpe_kernel<<<C * 16, THREADS>>>(tensor, bias, out);
}